// round 1
// baseline (speedup 1.0000x reference)
#include <cuda_runtime.h>
#include <cstdint>

#define T_STEPS 2048
#define BATCH   32
#define DIN     512
#define HID     512
#define GDIM    2048          // 4*H
#define NBLK    128           // persistent CTAs for recurrence
#define HPB     4             // hidden units per CTA
#define GROWS   16            // gate rows per CTA (4 gates * HPB)

// ---------------- scratch (static device allocs are the sanctioned scratch path) ----
__device__ float g_pre[(size_t)T_STEPS * GDIM * BATCH];   // [T][G][B], 512 MB
__device__ float g_hbuf[2][HID * BATCH];                  // h double buffer, [h][b]
__device__ unsigned int g_count;
__device__ volatile unsigned int g_phase;

// ---------------- init: reset barrier, transpose h0 into [h][b] ---------------------
__global__ void init_kernel(const float* __restrict__ h0) {
    int tid = blockIdx.x * blockDim.x + threadIdx.x;
    if (tid == 0) { g_count = 0; g_phase = 0; }
    for (int i = tid; i < HID * BATCH; i += blockDim.x * gridDim.x) {
        int h = i >> 5, b = i & 31;
        g_hbuf[0][i] = h0[b * HID + h];
    }
}

// ---------------- kernel 1: pre = x @ w_ih^T + b_ih, stored [T][G][B] ---------------
// C[m][n], m = t*32+b (65536), n = g (2048), K = 512. 64x64 tile, 4x4/thread, BK=32.
__global__ __launch_bounds__(256) void gemm_pre_kernel(
    const float* __restrict__ x, const float* __restrict__ w_ih,
    const float* __restrict__ b_ih)
{
    __shared__ float As[32][68];
    __shared__ float Bs[32][68];
    const int tid = threadIdx.x;
    const int m0 = blockIdx.y * 64;
    const int n0 = blockIdx.x * 64;
    const int lr = tid >> 3;          // 0..31
    const int lc = (tid & 7) * 4;     // 0..28
    const float* pA = x    + (size_t)(m0 + lr) * DIN + lc;
    const float* pB = w_ih + (size_t)(n0 + lr) * DIN + lc;
    const int ty = tid >> 4;          // m frag 0..15
    const int tx = tid & 15;          // n frag 0..15

    float acc[4][4];
    #pragma unroll
    for (int i = 0; i < 4; i++)
        #pragma unroll
        for (int j = 0; j < 4; j++) acc[i][j] = 0.f;

    for (int kt = 0; kt < DIN; kt += 32) {
        float4 a0 = *(const float4*)(pA + kt);
        float4 a1 = *(const float4*)(pA + kt + (size_t)32 * DIN);
        float4 b0 = *(const float4*)(pB + kt);
        float4 b1 = *(const float4*)(pB + kt + (size_t)32 * DIN);
        __syncthreads();
        As[lc+0][lr] = a0.x; As[lc+1][lr] = a0.y; As[lc+2][lr] = a0.z; As[lc+3][lr] = a0.w;
        As[lc+0][lr+32] = a1.x; As[lc+1][lr+32] = a1.y; As[lc+2][lr+32] = a1.z; As[lc+3][lr+32] = a1.w;
        Bs[lc+0][lr] = b0.x; Bs[lc+1][lr] = b0.y; Bs[lc+2][lr] = b0.z; Bs[lc+3][lr] = b0.w;
        Bs[lc+0][lr+32] = b1.x; Bs[lc+1][lr+32] = b1.y; Bs[lc+2][lr+32] = b1.z; Bs[lc+3][lr+32] = b1.w;
        __syncthreads();
        #pragma unroll
        for (int kk = 0; kk < 32; kk++) {
            float4 av = *(const float4*)&As[kk][ty * 4];
            float4 bv = *(const float4*)&Bs[kk][tx * 4];
            acc[0][0] += av.x * bv.x; acc[0][1] += av.x * bv.y; acc[0][2] += av.x * bv.z; acc[0][3] += av.x * bv.w;
            acc[1][0] += av.y * bv.x; acc[1][1] += av.y * bv.y; acc[1][2] += av.y * bv.z; acc[1][3] += av.y * bv.w;
            acc[2][0] += av.z * bv.x; acc[2][1] += av.z * bv.y; acc[2][2] += av.z * bv.z; acc[2][3] += av.z * bv.w;
            acc[3][0] += av.w * bv.x; acc[3][1] += av.w * bv.y; acc[3][2] += av.w * bv.z; acc[3][3] += av.w * bv.w;
        }
    }
    #pragma unroll
    for (int i = 0; i < 4; i++) {
        int m = m0 + ty * 4 + i;
        int t = m >> 5, b = m & 31;
        #pragma unroll
        for (int j = 0; j < 4; j++) {
            int n = n0 + tx * 4 + j;
            g_pre[((size_t)t * GDIM + n) * BATCH + b] = acc[i][j] + b_ih[n];
        }
    }
}

// ---------------- kernel 2: persistent recurrence -----------------------------------
// SMEM layout (floats): w_s[512*16] | h_s[512*32] | part[4*512] | gates[512] | c_s[128] | b_s[16]
#define SMEM_FLOATS (512*16 + 512*32 + 4*512 + 512 + 128 + 16)
#define SMEM_BYTES  (SMEM_FLOATS * 4)

__global__ __launch_bounds__(256, 1) void lstm_rec_kernel(
    const float* __restrict__ w_hh, const float* __restrict__ b_hh,
    const float* __restrict__ c0,   float* __restrict__ out,
    int write_finals)
{
    extern __shared__ float sm[];
    float* w_s   = sm;                       // [k][r]  512 x 16
    float* h_s   = w_s + 512 * 16;           // [k][b]  512 x 32
    float* part  = h_s + 512 * 32;           // [ks][flat] 4 x 512
    float* gates = part + 4 * 512;           // [flat]  512
    float* c_s   = gates + 512;              // [hh*32+b] 128
    float* b_s   = c_s + 128;                // [r] 16

    const int tid = threadIdx.x;
    const int hbase = blockIdx.x * HPB;

    // stage W_hh rows (i,f,g,o slices for our 4 hidden units), transposed [k][r]
    for (int idx = tid; idx < GROWS * 512; idx += 256) {
        int r = idx >> 9, k = idx & 511;
        int grow = (r >> 2) * HID + hbase + (r & 3);
        w_s[k * 16 + r] = w_hh[(size_t)grow * HID + k];
    }
    if (tid < GROWS) b_s[tid] = b_hh[(tid >> 2) * HID + hbase + (tid & 3)];
    if (tid < 128) {
        int hh = tid >> 5, b = tid & 31;
        c_s[tid] = c0[b * HID + hbase + hh];
    }

    // matvec mapping: 4-way k-split, 2 rows x 4 batches per thread
    const int warp = tid >> 5, lane = tid & 31;
    const int ks = warp >> 1;
    const int tile = ((warp & 1) << 5) + lane;   // 0..63
    const int r0 = (tile >> 3) * 2;              // even row in 0..14
    const int b0 = (tile & 7) * 4;               // 0..28

    // reduce mapping: 2 gate sums per thread
    const int f0 = tid * 2;
    const int rr = f0 >> 5, rb = f0 & 31;
    const size_t prebase = (size_t)((rr >> 2) * HID + hbase + (rr & 3)) * BATCH + rb;

    __syncthreads();

    for (int t = 0; t < T_STEPS; t++) {
        // stage h (must bypass L1: other CTAs wrote it this launch)
        const float4* hsrc = (const float4*)g_hbuf[t & 1];
        float4* hdst = (float4*)h_s;
        #pragma unroll
        for (int i = 0; i < (512 * 32 / 4) / 256; i++)
            hdst[tid + i * 256] = __ldcg(hsrc + tid + i * 256);

        // prefetch this thread's pre[t] values (latency hidden by matvec)
        const float* pre_t = g_pre + (size_t)t * GDIM * BATCH;
        float pg0 = pre_t[prebase];
        float pg1 = pre_t[prebase + 1];

        __syncthreads();

        // matvec partial: rows r0,r0+1 x batches b0..b0+3 over k in [ks*128, ks*128+128)
        float a00=0.f,a01=0.f,a02=0.f,a03=0.f,a10=0.f,a11=0.f,a12=0.f,a13=0.f;
        const float* wp = w_s + ks * 128 * 16 + r0;
        const float* hp = h_s + ks * 128 * 32 + b0;
        #pragma unroll 8
        for (int k = 0; k < 128; k++) {
            float2 wv = *(const float2*)(wp + k * 16);
            float4 hv = *(const float4*)(hp + k * 32);
            a00 += wv.x * hv.x; a01 += wv.x * hv.y; a02 += wv.x * hv.z; a03 += wv.x * hv.w;
            a10 += wv.y * hv.x; a11 += wv.y * hv.y; a12 += wv.y * hv.z; a13 += wv.y * hv.w;
        }
        *(float4*)(part + ks * 512 + (r0    ) * 32 + b0) = make_float4(a00, a01, a02, a03);
        *(float4*)(part + ks * 512 + (r0 + 1) * 32 + b0) = make_float4(a10, a11, a12, a13);
        __syncthreads();

        // reduce k-splits + pre + b_hh
        gates[f0]     = part[f0]     + part[512 + f0]     + part[1024 + f0]     + part[1536 + f0]     + pg0 + b_s[rr];
        gates[f0 + 1] = part[f0 + 1] + part[512 + f0 + 1] + part[1024 + f0 + 1] + part[1536 + f0 + 1] + pg1 + b_s[rr];
        __syncthreads();

        // elementwise LSTM update for our (hh, b) slice
        if (tid < 128) {
            int hh = tid >> 5, b = tid & 31;
            float iv = gates[(0 * 4 + hh) * 32 + b];
            float fv = gates[(1 * 4 + hh) * 32 + b];
            float gv = gates[(2 * 4 + hh) * 32 + b];
            float ov = gates[(3 * 4 + hh) * 32 + b];
            iv = 1.f / (1.f + __expf(-iv));
            fv = 1.f / (1.f + __expf(-fv));
            ov = 1.f / (1.f + __expf(-ov));
            gv = tanhf(gv);
            float c = fv * c_s[tid] + iv * gv;
            c_s[tid] = c;
            float h = ov * tanhf(c);
            g_hbuf[(t + 1) & 1][(hbase + hh) * 32 + b] = h;
            out[(size_t)t * BATCH * HID + b * HID + hbase + hh] = h;
            if (write_finals && t == T_STEPS - 1) {
                out[(size_t)T_STEPS * BATCH * HID + b * HID + hbase + hh] = h;
                out[(size_t)T_STEPS * BATCH * HID + BATCH * HID + b * HID + hbase + hh] = c;
            }
        }
        __syncthreads();

        // grid-wide barrier (monotonic; reset per launch by init_kernel)
        if (tid == 0) {
            __threadfence();
            unsigned old = atomicAdd(&g_count, 1u);
            if (old == (unsigned)(NBLK) * (unsigned)(t + 1) - 1u) {
                g_phase = (unsigned)(t + 1);
            } else {
                while (g_phase < (unsigned)(t + 1)) { }
            }
        }
        __syncthreads();
    }
}

// ---------------- launch ------------------------------------------------------------
extern "C" void kernel_launch(void* const* d_in, const int* in_sizes, int n_in,
                              void* d_out, int out_size) {
    const float* x    = (const float*)d_in[0];
    const float* h0   = (const float*)d_in[1];
    const float* c0   = (const float*)d_in[2];
    const float* w_ih = (const float*)d_in[3];
    const float* w_hh = (const float*)d_in[4];
    const float* b_ih = (const float*)d_in[5];
    const float* b_hh = (const float*)d_in[6];
    float* out = (float*)d_out;

    const int main_sz = T_STEPS * BATCH * HID;
    int write_finals = (out_size >= main_sz + 2 * BATCH * HID) ? 1 : 0;

    init_kernel<<<1, 256>>>(h0);

    dim3 ggrid(GDIM / 64, (T_STEPS * BATCH) / 64);
    gemm_pre_kernel<<<ggrid, 256>>>(x, w_ih, b_ih);

    cudaFuncSetAttribute(lstm_rec_kernel,
                         cudaFuncAttributeMaxDynamicSharedMemorySize, SMEM_BYTES);
    lstm_rec_kernel<<<NBLK, 256, SMEM_BYTES>>>(w_hh, b_hh, c0, out, write_finals);
}

// round 3
// speedup vs baseline: 1.0654x; 1.0654x over previous
#include <cuda_runtime.h>
#include <cstdint>

#define T_STEPS 2048
#define BATCH   32
#define DIN     512
#define HID     512
#define GDIM    2048          // 4*H
#define NBLK    128           // persistent CTAs for recurrence
#define HPB     4             // hidden units per CTA
#define GROWS   16            // gate rows per CTA (4 gates * HPB)

// ---------------- scratch ----------------
__device__ float g_pre[(size_t)T_STEPS * GDIM * BATCH];   // [T][G][B]
__device__ float g_hbuf[2][HID * BATCH];                  // h double buffer, [h][b]
__device__ unsigned int g_count;
__device__ volatile unsigned int g_phase;

// ---------------- init: reset barrier, transpose h0 into [h][b] ----------------
__global__ void init_kernel(const float* __restrict__ h0) {
    int tid = blockIdx.x * blockDim.x + threadIdx.x;
    if (tid == 0) { g_count = 0; g_phase = 0; }
    for (int i = tid; i < HID * BATCH; i += blockDim.x * gridDim.x) {
        int h = i >> 5, b = i & 31;
        g_hbuf[0][i] = h0[b * HID + h];
    }
}

// ---------------- helpers ----------------
__device__ __forceinline__ unsigned int f2tf32(float f) {
    unsigned int u;
    asm("cvt.rna.tf32.f32 %0, %1;" : "=r"(u) : "f"(f));
    return u;
}

__device__ __forceinline__ void mma_tf32(float* c, const unsigned int* a, const unsigned int* b) {
    asm("mma.sync.aligned.m16n8k8.row.col.f32.tf32.tf32.f32 "
        "{%0,%1,%2,%3},{%4,%5,%6,%7},{%8,%9},{%0,%1,%2,%3};"
        : "+f"(c[0]), "+f"(c[1]), "+f"(c[2]), "+f"(c[3])
        : "r"(a[0]), "r"(a[1]), "r"(a[2]), "r"(a[3]), "r"(b[0]), "r"(b[1]));
}

__device__ __forceinline__ void ffma2(unsigned long long& d, unsigned long long a, unsigned long long b) {
    asm("fma.rn.f32x2 %0, %1, %2, %0;" : "+l"(d) : "l"(a), "l"(b));
}

// ---------------- kernel 1: pre = x @ w_ih^T + b_ih via tf32 tensor cores -----------
// C[m][n], m = t*32+b (65536), n = g (2048), K = 512.
// CTA tile 128x64, BK=32, 8 warps (4 in M x 2 in N), warp tile 32x32, m16n8k8.
#define BM 128
#define BN 64
#define BK 32
#define APITCH 33
#define CPITCH 65

__global__ __launch_bounds__(256) void gemm_pre_tc(
    const float* __restrict__ x, const float* __restrict__ w_ih,
    const float* __restrict__ b_ih)
{
    // union: A_s(128x33 u32) + B_s(64x33 u32) = 6336 u32;  C_s = 128x65 float = 8320
    __shared__ __align__(16) float smem_raw[BM * CPITCH];
    unsigned int* A_s = (unsigned int*)smem_raw;
    unsigned int* B_s = A_s + BM * APITCH;
    float* C_s = smem_raw;

    const int tid  = threadIdx.x;
    const int m0   = blockIdx.y * BM;
    const int n0   = blockIdx.x * BN;
    const int warp = tid >> 5, lane = tid & 31;
    const int g  = lane >> 2;       // group id 0..7
    const int tg = lane & 3;        // thread-in-group
    const int warp_m = (warp >> 1) * 32;
    const int warp_n = (warp & 1) * 32;

    const int lr = tid >> 3;        // 0..31
    const int lc = (tid & 7) * 4;   // 0,4,...,28

    float cfr[2][4][4];
    #pragma unroll
    for (int mi = 0; mi < 2; mi++)
        #pragma unroll
        for (int ni = 0; ni < 4; ni++)
            #pragma unroll
            for (int q = 0; q < 4; q++) cfr[mi][ni][q] = 0.f;

    for (int kt = 0; kt < DIN; kt += BK) {
        // global loads
        float4 av[4], bv[2];
        #pragma unroll
        for (int i = 0; i < 4; i++)
            av[i] = *(const float4*)(x + (size_t)(m0 + lr + 32 * i) * DIN + kt + lc);
        #pragma unroll
        for (int i = 0; i < 2; i++)
            bv[i] = *(const float4*)(w_ih + (size_t)(n0 + lr + 32 * i) * DIN + kt + lc);
        __syncthreads();
        #pragma unroll
        for (int i = 0; i < 4; i++) {
            int row = lr + 32 * i;
            A_s[row * APITCH + lc + 0] = f2tf32(av[i].x);
            A_s[row * APITCH + lc + 1] = f2tf32(av[i].y);
            A_s[row * APITCH + lc + 2] = f2tf32(av[i].z);
            A_s[row * APITCH + lc + 3] = f2tf32(av[i].w);
        }
        #pragma unroll
        for (int i = 0; i < 2; i++) {
            int row = lr + 32 * i;
            B_s[row * APITCH + lc + 0] = f2tf32(bv[i].x);
            B_s[row * APITCH + lc + 1] = f2tf32(bv[i].y);
            B_s[row * APITCH + lc + 2] = f2tf32(bv[i].z);
            B_s[row * APITCH + lc + 3] = f2tf32(bv[i].w);
        }
        __syncthreads();

        #pragma unroll
        for (int kk = 0; kk < BK / 8; kk++) {
            const int kb = kk * 8;
            unsigned int a[2][4], bf[4][2];
            #pragma unroll
            for (int mi = 0; mi < 2; mi++) {
                int rb = warp_m + mi * 16 + g;
                a[mi][0] = A_s[(rb    ) * APITCH + kb + tg];
                a[mi][1] = A_s[(rb + 8) * APITCH + kb + tg];
                a[mi][2] = A_s[(rb    ) * APITCH + kb + tg + 4];
                a[mi][3] = A_s[(rb + 8) * APITCH + kb + tg + 4];
            }
            #pragma unroll
            for (int ni = 0; ni < 4; ni++) {
                int nb = warp_n + ni * 8 + g;
                bf[ni][0] = B_s[nb * APITCH + kb + tg];
                bf[ni][1] = B_s[nb * APITCH + kb + tg + 4];
            }
            #pragma unroll
            for (int mi = 0; mi < 2; mi++)
                #pragma unroll
                for (int ni = 0; ni < 4; ni++)
                    mma_tf32(cfr[mi][ni], a[mi], bf[ni]);
        }
    }

    // epilogue: frags -> SMEM -> coalesced global stores
    __syncthreads();
    #pragma unroll
    for (int mi = 0; mi < 2; mi++) {
        #pragma unroll
        for (int ni = 0; ni < 4; ni++) {
            int row0 = warp_m + mi * 16 + g;
            int col0 = warp_n + ni * 8 + 2 * tg;
            C_s[(row0    ) * CPITCH + col0    ] = cfr[mi][ni][0];
            C_s[(row0    ) * CPITCH + col0 + 1] = cfr[mi][ni][1];
            C_s[(row0 + 8) * CPITCH + col0    ] = cfr[mi][ni][2];
            C_s[(row0 + 8) * CPITCH + col0 + 1] = cfr[mi][ni][3];
        }
    }
    __syncthreads();

    const int tq = warp >> 1;          // local 32-row block => one t per block
    const int nh = warp & 1;           // 32-col half
    const int lm = tq * 32 + lane;     // b = lane
    const int t  = (m0 + lm) >> 5;
    const int b  = lane;
    #pragma unroll 4
    for (int j = 0; j < 32; j++) {
        int nl = nh * 32 + j;
        int gi = n0 + nl;
        g_pre[((size_t)t * GDIM + gi) * BATCH + b] = C_s[lm * CPITCH + nl] + __ldg(b_ih + gi);
    }
}

// ---------------- kernel 2: persistent recurrence (FFMA2 matvec) --------------------
// SMEM (bytes): w2 [512][16] float2 = 64KB | h 512*32 f = 64KB | part 4*512 f = 8KB
//               gates 512 f = 2KB | c 128 f | b 16 f
#define SMEM_BYTES (512*16*8 + 512*32*4 + 4*512*4 + 512*4 + 128*4 + 16*4)

__global__ __launch_bounds__(256, 1) void lstm_rec_kernel(
    const float* __restrict__ w_hh, const float* __restrict__ b_hh,
    const float* __restrict__ c0,   float* __restrict__ out,
    int write_finals)
{
    extern __shared__ float sm[];
    float2* w2_s = (float2*)sm;                    // [k][r] duplicated pairs, 512 x 16
    float* h_s   = sm + 512 * 16 * 2;              // [k][b] 512 x 32
    float* part  = h_s + 512 * 32;                 // [ks][flat] 4 x 512
    float* gates = part + 4 * 512;                 // [flat] 512
    float* c_s   = gates + 512;                    // 128
    float* b_s   = c_s + 128;                      // 16

    const int tid = threadIdx.x;
    const int hbase = blockIdx.x * HPB;

    // stage W_hh rows transposed and duplicated: w2_s[k][r] = {w, w}
    for (int idx = tid; idx < GROWS * 512; idx += 256) {
        int r = idx >> 9, k = idx & 511;
        int grow = (r >> 2) * HID + hbase + (r & 3);
        float v = w_hh[(size_t)grow * HID + k];
        w2_s[k * 16 + r] = make_float2(v, v);
    }
    if (tid < GROWS) b_s[tid] = b_hh[(tid >> 2) * HID + hbase + (tid & 3)];
    if (tid < 128) {
        int hh = tid >> 5, b = tid & 31;
        c_s[tid] = c0[b * HID + hbase + hh];
    }

    const int warp = tid >> 5, lane = tid & 31;
    const int ks = warp >> 1;                    // k-split 0..3
    const int tile = ((warp & 1) << 5) + lane;   // 0..63
    const int r0 = (tile >> 3) * 2;              // even row 0..14
    const int b0 = (tile & 7) * 4;               // 0..28

    const int f0 = tid * 2;
    const int rr = f0 >> 5, rb = f0 & 31;
    const size_t prebase = (size_t)((rr >> 2) * HID + hbase + (rr & 3)) * BATCH + rb;

    const float2* w2base = w2_s + ks * 128 * 16 + r0;
    const float*  hbse   = h_s  + ks * 128 * 32 + b0;

    __syncthreads();

    for (int t = 0; t < T_STEPS; t++) {
        // stage h (bypass L1: other CTAs wrote it this launch)
        const float4* hsrc = (const float4*)g_hbuf[t & 1];
        float4* hdst = (float4*)h_s;
        #pragma unroll
        for (int i = 0; i < (512 * 32 / 4) / 256; i++)
            hdst[tid + i * 256] = __ldcg(hsrc + tid + i * 256);

        const float* pre_t = g_pre + (size_t)t * GDIM * BATCH;
        float pg0 = pre_t[prebase];
        float pg1 = pre_t[prebase + 1];

        __syncthreads();

        // matvec with packed f32x2 FMA: rows {r0,r0+1} x batches {b0..b0+3}
        unsigned long long a00 = 0ull, a01 = 0ull, a10 = 0ull, a11 = 0ull;
        #pragma unroll 8
        for (int k = 0; k < 128; k++) {
            ulonglong2 wv = *reinterpret_cast<const ulonglong2*>(w2base + (size_t)k * 16);
            ulonglong2 hv = *reinterpret_cast<const ulonglong2*>(hbse + (size_t)k * 32);
            ffma2(a00, wv.x, hv.x);
            ffma2(a01, wv.x, hv.y);
            ffma2(a10, wv.y, hv.x);
            ffma2(a11, wv.y, hv.y);
        }
        {
            ulonglong2 s0; s0.x = a00; s0.y = a01;
            ulonglong2 s1; s1.x = a10; s1.y = a11;
            *reinterpret_cast<ulonglong2*>(part + ks * 512 + (r0    ) * 32 + b0) = s0;
            *reinterpret_cast<ulonglong2*>(part + ks * 512 + (r0 + 1) * 32 + b0) = s1;
        }
        __syncthreads();

        // reduce k-splits + pre + b_hh
        gates[f0]     = part[f0]     + part[512 + f0]     + part[1024 + f0]     + part[1536 + f0]     + pg0 + b_s[rr];
        gates[f0 + 1] = part[f0 + 1] + part[512 + f0 + 1] + part[1024 + f0 + 1] + part[1536 + f0 + 1] + pg1 + b_s[rr];
        __syncthreads();

        // elementwise LSTM update
        if (tid < 128) {
            int hh = tid >> 5, b = tid & 31;
            float iv = gates[(0 * 4 + hh) * 32 + b];
            float fv = gates[(1 * 4 + hh) * 32 + b];
            float gv = gates[(2 * 4 + hh) * 32 + b];
            float ov = gates[(3 * 4 + hh) * 32 + b];
            iv = 1.f / (1.f + __expf(-iv));
            fv = 1.f / (1.f + __expf(-fv));
            ov = 1.f / (1.f + __expf(-ov));
            gv = tanhf(gv);
            float c = fv * c_s[tid] + iv * gv;
            c_s[tid] = c;
            float h = ov * tanhf(c);
            g_hbuf[(t + 1) & 1][(hbase + hh) * 32 + b] = h;
            out[(size_t)t * BATCH * HID + b * HID + hbase + hh] = h;
            if (write_finals && t == T_STEPS - 1) {
                out[(size_t)T_STEPS * BATCH * HID + b * HID + hbase + hh] = h;
                out[(size_t)T_STEPS * BATCH * HID + BATCH * HID + b * HID + hbase + hh] = c;
            }
        }
        __syncthreads();

        // grid-wide barrier (monotonic)
        if (tid == 0) {
            __threadfence();
            unsigned old = atomicAdd(&g_count, 1u);
            if (old == (unsigned)(NBLK) * (unsigned)(t + 1) - 1u) {
                g_phase = (unsigned)(t + 1);
            } else {
                while (g_phase < (unsigned)(t + 1)) { }
            }
        }
        __syncthreads();
    }
}

// ---------------- launch ----------------
extern "C" void kernel_launch(void* const* d_in, const int* in_sizes, int n_in,
                              void* d_out, int out_size) {
    const float* x    = (const float*)d_in[0];
    const float* h0   = (const float*)d_in[1];
    const float* c0   = (const float*)d_in[2];
    const float* w_ih = (const float*)d_in[3];
    const float* w_hh = (const float*)d_in[4];
    const float* b_ih = (const float*)d_in[5];
    const float* b_hh = (const float*)d_in[6];
    float* out = (float*)d_out;

    const int main_sz = T_STEPS * BATCH * HID;
    int write_finals = (out_size >= main_sz + 2 * BATCH * HID) ? 1 : 0;

    init_kernel<<<1, 256>>>(h0);

    dim3 ggrid(GDIM / BN, (T_STEPS * BATCH) / BM);
    gemm_pre_tc<<<ggrid, 256>>>(x, w_ih, b_ih);

    cudaFuncSetAttribute(lstm_rec_kernel,
                         cudaFuncAttributeMaxDynamicSharedMemorySize, SMEM_BYTES);
    lstm_rec_kernel<<<NBLK, 256, SMEM_BYTES>>>(w_hh, b_hh, c0, out, write_finals);
}